// round 1
// baseline (speedup 1.0000x reference)
#include <cuda_runtime.h>
#include <math.h>

// Problem constants
#define BATCH   2
#define NSEQ    2048
#define DMODEL  1024
#define NHEADS  16
#define DHEAD   64
#define MROWS   (BATCH * NSEQ)   // 4096

// Device scratch (static __device__ arrays: allowed; no runtime allocation)
__device__ float g_q[MROWS * DMODEL];
__device__ float g_k[MROWS * DMODEL];
__device__ float g_v[MROWS * DMODEL];
__device__ float g_attn[MROWS * DMODEL];

// ---------------------------------------------------------------------------
// Tiled fp32 GEMM with bias: C[M,N] = (A (+A2)) @ B + bias
// BM=128, BN=128, BK=8, 256 threads, 8x8 microtile per thread.
// ---------------------------------------------------------------------------
template <bool FUSE_ADD>
__global__ __launch_bounds__(256)
void sgemm_bias(const float* __restrict__ A, const float* __restrict__ A2,
                const float* __restrict__ B, const float* __restrict__ bias,
                float* __restrict__ C, int M, int N, int K)
{
    __shared__ float As[8][128];
    __shared__ float Bs[8][128];

    const int tid  = threadIdx.x;
    const int brow = blockIdx.y * 128;
    const int bcol = blockIdx.x * 128;

    const int aRow = tid >> 1;          // 0..127
    const int aK   = (tid & 1) * 4;     // 0 or 4
    const int bK   = tid >> 5;          // 0..7
    const int bCol = (tid & 31) * 4;    // 0..124
    const int tRow = (tid >> 4) * 8;    // 0..120
    const int tCol = (tid & 15) * 8;    // 0..120

    float acc[8][8];
#pragma unroll
    for (int i = 0; i < 8; i++)
#pragma unroll
        for (int j = 0; j < 8; j++) acc[i][j] = 0.0f;

    const float* aPtr  = A + (size_t)(brow + aRow) * K + aK;
    const float* a2Ptr = FUSE_ADD ? (A2 + (size_t)(brow + aRow) * K + aK) : nullptr;

    for (int k0 = 0; k0 < K; k0 += 8) {
        float4 av = *(const float4*)(aPtr + k0);
        if (FUSE_ADD) {
            float4 w = *(const float4*)(a2Ptr + k0);
            av.x += w.x; av.y += w.y; av.z += w.z; av.w += w.w;
        }
        As[aK + 0][aRow] = av.x;
        As[aK + 1][aRow] = av.y;
        As[aK + 2][aRow] = av.z;
        As[aK + 3][aRow] = av.w;

        *(float4*)&Bs[bK][bCol] =
            *(const float4*)&B[(size_t)(k0 + bK) * N + bcol + bCol];

        __syncthreads();

#pragma unroll
        for (int kk = 0; kk < 8; kk++) {
            float4 ra0 = *(const float4*)&As[kk][tRow];
            float4 ra1 = *(const float4*)&As[kk][tRow + 4];
            float4 rb0 = *(const float4*)&Bs[kk][tCol];
            float4 rb1 = *(const float4*)&Bs[kk][tCol + 4];
            float ra[8] = {ra0.x, ra0.y, ra0.z, ra0.w, ra1.x, ra1.y, ra1.z, ra1.w};
            float rb[8] = {rb0.x, rb0.y, rb0.z, rb0.w, rb1.x, rb1.y, rb1.z, rb1.w};
#pragma unroll
            for (int i = 0; i < 8; i++)
#pragma unroll
                for (int j = 0; j < 8; j++)
                    acc[i][j] = fmaf(ra[i], rb[j], acc[i][j]);
        }
        __syncthreads();
    }

#pragma unroll
    for (int i = 0; i < 8; i++) {
        float* cp = C + (size_t)(brow + tRow + i) * N + bcol + tCol;
#pragma unroll
        for (int j = 0; j < 8; j++)
            cp[j] = acc[i][j] + bias[bcol + tCol + j];
    }
}

// ---------------------------------------------------------------------------
// In-place LayerNorm over rows of length 1024. One block (256 thr) per row.
// ---------------------------------------------------------------------------
__global__ __launch_bounds__(256)
void ln_kernel(float* __restrict__ qio, const float* __restrict__ gamma,
               const float* __restrict__ beta)
{
    const int row = blockIdx.x;
    const int tid = threadIdx.x;
    float* rowp = qio + (size_t)row * DMODEL;

    float4 xv = *(const float4*)&rowp[tid * 4];
    float s  = xv.x + xv.y + xv.z + xv.w;
    float s2 = xv.x * xv.x + xv.y * xv.y + xv.z * xv.z + xv.w * xv.w;

#pragma unroll
    for (int o = 16; o > 0; o >>= 1) {
        s  += __shfl_xor_sync(0xffffffffu, s, o);
        s2 += __shfl_xor_sync(0xffffffffu, s2, o);
    }

    __shared__ float ws[8], ws2[8];
    if ((tid & 31) == 0) { ws[tid >> 5] = s; ws2[tid >> 5] = s2; }
    __syncthreads();

    float tot = 0.f, tot2 = 0.f;
#pragma unroll
    for (int i = 0; i < 8; i++) { tot += ws[i]; tot2 += ws2[i]; }

    const float inv = 1.0f / (float)DMODEL;
    float mu  = tot * inv;
    float var = tot2 * inv - mu * mu;
    float rs  = rsqrtf(var + 1e-5f);

    float4 gv = *(const float4*)&gamma[tid * 4];
    float4 bv = *(const float4*)&beta[tid * 4];
    float4 yv;
    yv.x = (xv.x - mu) * rs * gv.x + bv.x;
    yv.y = (xv.y - mu) * rs * gv.y + bv.y;
    yv.z = (xv.z - mu) * rs * gv.z + bv.z;
    yv.w = (xv.w - mu) * rs * gv.w + bv.w;
    *(float4*)&rowp[tid * 4] = yv;
}

// ---------------------------------------------------------------------------
// Flash-attention style kernel. One block per (64 q-rows, head, batch).
// k-tiles of 32. Online softmax, fp32 throughout.
// Thread map: rp = tid>>3 (row pair), c = tid&7 (interleaved columns).
// Strides chosen conflict-free for all LDS patterns.
// ---------------------------------------------------------------------------
__global__ __launch_bounds__(256)
void attn_kernel(const float* __restrict__ q, const float* __restrict__ k,
                 const float* __restrict__ v, float* __restrict__ o)
{
    __shared__ float Qs[64][68];
    __shared__ float Ks[32][68];
    __shared__ float Vs[32][68];
    __shared__ float Ps[64][36];

    const int tid = threadIdx.x;
    const int b = blockIdx.z, h = blockIdx.y;
    const int q0 = blockIdx.x * 64;

    const float* qbase = q + ((size_t)(b * NSEQ + q0)) * DMODEL + h * DHEAD;
    const float* kbase = k + ((size_t)(b * NSEQ)) * DMODEL + h * DHEAD;
    const float* vbase = v + ((size_t)(b * NSEQ)) * DMODEL + h * DHEAD;

    // Load Q tile (64x64), scaled by d^-0.5 = 0.125
    const float qscale = 0.125f;
#pragma unroll
    for (int it = 0; it < 4; it++) {
        int idx = tid + it * 256;          // 0..1023 float4s
        int r  = idx >> 4;
        int d4 = (idx & 15) * 4;
        float4 val = *(const float4*)&qbase[(size_t)r * DMODEL + d4];
        val.x *= qscale; val.y *= qscale; val.z *= qscale; val.w *= qscale;
        *(float4*)&Qs[r][d4] = val;
    }

    const int rp = tid >> 3;       // 0..31
    const int c  = tid & 7;        // 0..7
    const int r0 = rp * 2;

    float m[2] = {-1e30f, -1e30f};
    float l[2] = {0.f, 0.f};
    float O[2][8];
#pragma unroll
    for (int rr = 0; rr < 2; rr++)
#pragma unroll
        for (int jj = 0; jj < 8; jj++) O[rr][jj] = 0.f;

    for (int k0 = 0; k0 < NSEQ; k0 += 32) {
        __syncthreads();  // previous O-phase done reading Vs/Ps; Qs ready (iter 0)

        // Load K,V tiles (32x64 each) = 512 float4 each
#pragma unroll
        for (int it = 0; it < 2; it++) {
            int idx = tid + it * 256;      // 0..511
            int kc = idx >> 4;
            int d4 = (idx & 15) * 4;
            *(float4*)&Ks[kc][d4] = *(const float4*)&kbase[(size_t)(k0 + kc) * DMODEL + d4];
            *(float4*)&Vs[kc][d4] = *(const float4*)&vbase[(size_t)(k0 + kc) * DMODEL + d4];
        }
        __syncthreads();

        // S = Q K^T : each thread: 2 rows x 4 key-cols (kc = c + 8*i)
        float s[2][4] = {{0.f,0.f,0.f,0.f},{0.f,0.f,0.f,0.f}};
#pragma unroll 4
        for (int d = 0; d < 64; d++) {
            float q0v = Qs[r0][d];
            float q1v = Qs[r0 + 1][d];
#pragma unroll
            for (int i = 0; i < 4; i++) {
                float kv = Ks[c + 8 * i][d];
                s[0][i] = fmaf(q0v, kv, s[0][i]);
                s[1][i] = fmaf(q1v, kv, s[1][i]);
            }
        }

        // Online softmax update per row
#pragma unroll
        for (int rr = 0; rr < 2; rr++) {
            float tm = fmaxf(fmaxf(s[rr][0], s[rr][1]), fmaxf(s[rr][2], s[rr][3]));
            tm = fmaxf(tm, __shfl_xor_sync(0xffffffffu, tm, 1));
            tm = fmaxf(tm, __shfl_xor_sync(0xffffffffu, tm, 2));
            tm = fmaxf(tm, __shfl_xor_sync(0xffffffffu, tm, 4));

            float mn = fmaxf(m[rr], tm);
            float alpha = __expf(m[rr] - mn);
            float p[4], ps = 0.f;
#pragma unroll
            for (int i = 0; i < 4; i++) {
                p[i] = __expf(s[rr][i] - mn);
                ps += p[i];
            }
            ps += __shfl_xor_sync(0xffffffffu, ps, 1);
            ps += __shfl_xor_sync(0xffffffffu, ps, 2);
            ps += __shfl_xor_sync(0xffffffffu, ps, 4);

            l[rr] = l[rr] * alpha + ps;
            m[rr] = mn;
#pragma unroll
            for (int jj = 0; jj < 8; jj++) O[rr][jj] *= alpha;
#pragma unroll
            for (int i = 0; i < 4; i++) Ps[r0 + rr][c + 8 * i] = p[i];
        }
        __syncthreads();

        // O += P @ V : each thread 2 rows x 8 cols (j = c + 8*jj)
#pragma unroll 4
        for (int kc = 0; kc < 32; kc++) {
            float p0 = Ps[r0][kc];
            float p1 = Ps[r0 + 1][kc];
#pragma unroll
            for (int jj = 0; jj < 8; jj++) {
                float vv = Vs[kc][c + 8 * jj];
                O[0][jj] = fmaf(p0, vv, O[0][jj]);
                O[1][jj] = fmaf(p1, vv, O[1][jj]);
            }
        }
    }

    // Write out: o = O / (1e-8 + l)
    float* obase = o + ((size_t)(b * NSEQ + q0)) * DMODEL + h * DHEAD;
#pragma unroll
    for (int rr = 0; rr < 2; rr++) {
        float inv = 1.0f / (1e-8f + l[rr]);
#pragma unroll
        for (int jj = 0; jj < 8; jj++)
            obase[(size_t)(r0 + rr) * DMODEL + c + 8 * jj] = O[rr][jj] * inv;
    }
}

// ---------------------------------------------------------------------------
// Launch: QKV GEMMs -> LN(q) -> attention -> (attn + q_norm) @ Wo + bo
// ---------------------------------------------------------------------------
extern "C" void kernel_launch(void* const* d_in, const int* in_sizes, int n_in,
                              void* d_out, int out_size)
{
    (void)in_sizes; (void)n_in; (void)out_size;
    const float* x    = (const float*)d_in[0];
    const float* Wq   = (const float*)d_in[1];
    const float* bq   = (const float*)d_in[2];
    const float* Wk   = (const float*)d_in[3];
    const float* bk   = (const float*)d_in[4];
    const float* Wv   = (const float*)d_in[5];
    const float* bv   = (const float*)d_in[6];
    const float* Wo   = (const float*)d_in[7];
    const float* bo   = (const float*)d_in[8];
    const float* ln_g = (const float*)d_in[9];
    const float* ln_b = (const float*)d_in[10];
    float* out = (float*)d_out;

    float *qp, *kp, *vp, *ap;
    cudaGetSymbolAddress((void**)&qp, g_q);
    cudaGetSymbolAddress((void**)&kp, g_k);
    cudaGetSymbolAddress((void**)&vp, g_v);
    cudaGetSymbolAddress((void**)&ap, g_attn);

    dim3 ggrid(DMODEL / 128, MROWS / 128);  // (8, 32)

    sgemm_bias<false><<<ggrid, 256>>>(x, nullptr, Wq, bq, qp, MROWS, DMODEL, DMODEL);
    sgemm_bias<false><<<ggrid, 256>>>(x, nullptr, Wk, bk, kp, MROWS, DMODEL, DMODEL);
    sgemm_bias<false><<<ggrid, 256>>>(x, nullptr, Wv, bv, vp, MROWS, DMODEL, DMODEL);

    ln_kernel<<<MROWS, 256>>>(qp, ln_g, ln_b);

    attn_kernel<<<dim3(NSEQ / 64, NHEADS, BATCH), 256>>>(qp, kp, vp, ap);

    sgemm_bias<true><<<ggrid, 256>>>(ap, qp, Wo, bo, out, MROWS, DMODEL, DMODEL);
}